// round 1
// baseline (speedup 1.0000x reference)
#include <cuda_runtime.h>

#define HH 256
#define WW 512
#define CC 32
#define BB 2
#define HL (HH/4)
#define WL (WW/4)

// Tile: 32 wide x 8 tall pixels per CTA, 256 threads, 1 thread = 1 pixel.
// LR blocks covered: 8 wide x 2 tall; lr neighborhood needed: 10 x 4 blocks.
__global__ void __launch_bounds__(256, 2)
erc_kernel(const float* __restrict__ lr, const float* __restrict__ hr,
           const float* __restrict__ w0, const float* __restrict__ w1,
           const float* __restrict__ w2, const float* __restrict__ w3,
           float* __restrict__ out)
{
    __shared__ __align__(16) float s_w0T[66*32];    // [k][o]  (w0 transposed)
    __shared__ __align__(16) float s_w1[16*32];     // [o][k]
    __shared__ __align__(16) float s_w2[8*16];      // [o][k]
    __shared__ __align__(16) float s_w3[8];
    __shared__ __align__(16) float s_bias[16*9*32]; // [par][d][o]  distance-matrix part of layer0
    __shared__ __align__(16) float s_lrvec[40*32];  // [j*10+i][c]  lr feature vectors (clamped nbhd)
    __shared__ __align__(16) float s_lrproj[40*32]; // [j*10+i][o]  W0_lr @ lrvec
    __shared__ float s_logit[9*256];

    const int tid = threadIdx.x;
    const int b  = blockIdx.z;
    const int tx = tid & 31, ty = tid >> 5;
    const int h = blockIdx.y * 8 + ty;
    const int w = blockIdx.x * 32 + tx;

    // ---------------- Phase A: stage weights + lr vectors ----------------
    for (int idx = tid; idx < 66*32; idx += 256) {
        int k = idx >> 5, o = idx & 31;
        s_w0T[idx] = w0[o*66 + k];
    }
    for (int idx = tid; idx < 16*32; idx += 256) s_w1[idx] = w1[idx];
    if (tid < 8*16) s_w2[tid] = w2[tid];
    if (tid < 8)    s_w3[tid] = w3[tid];
    {
        const int y0 = blockIdx.y * 2 - 1;
        const int x0 = blockIdx.x * 8 - 1;
        for (int idx = tid; idx < 40*32; idx += 256) {
            int c = idx & 31, pos = idx >> 5;
            int j = pos / 10, i = pos - j*10;
            int yy = min(max(y0 + j, 0), HL - 1);   // clamped loads are only
            int xx = min(max(x0 + i, 0), WL - 1);   // consumed by masked dirs
            s_lrvec[idx] = lr[(((size_t)b*CC + c)*HL + yy)*WL + xx];
        }
    }
    __syncthreads();

    // ------- Phase B: bias table (distance part) + lr projections -------
    // direction order: c, l, r, t, b, lt, rt, lb, rb
    // dA code per dir (width ch):  0=x[px], 1=4-px, 2=px+1
    // dB code per dir (height ch): 0=x[py], 1=4-py, 2=py+1
    for (int idx = tid; idx < 16*9*32; idx += 256) {
        int o = idx & 31;
        int r = idx >> 5;
        int d = r % 9, par = r / 9;
        int py = par >> 2, px = par & 3;
        const unsigned CA = (0u<<0)|(1u<<2)|(2u<<4)|(0u<<6)|(0u<<8)|(1u<<10)|(2u<<12)|(0u<<14)|(0u<<16);
        const unsigned CB = (0u<<0)|(0u<<2)|(0u<<4)|(1u<<6)|(2u<<8)|(0u<<10)|(0u<<12)|(1u<<14)|(2u<<16);
        int ca = (CA >> (2*d)) & 3, cb = (CB >> (2*d)) & 3;
        float dA = (ca == 0) ? (float)((px < 2) ? px - 2 : px - 1)
                 : (ca == 1) ? (float)(4 - px) : (float)(px + 1);
        float dB = (cb == 0) ? (float)((py < 2) ? py - 2 : py - 1)
                 : (cb == 1) ? (float)(4 - py) : (float)(py + 1);
        s_bias[idx] = dA * s_w0T[64*32 + o] + dB * s_w0T[65*32 + o];
    }
    for (int idx = tid; idx < 40*32; idx += 256) {
        int o = idx & 31, pos = idx >> 5;
        const float4* v4 = (const float4*)&s_lrvec[pos*32];
        float acc = 0.f;
#pragma unroll
        for (int c4 = 0; c4 < 8; ++c4) {
            float4 v = v4[c4];
            acc = fmaf(v.x, s_w0T[(c4*4+0)*32 + o], acc);
            acc = fmaf(v.y, s_w0T[(c4*4+1)*32 + o], acc);
            acc = fmaf(v.z, s_w0T[(c4*4+2)*32 + o], acc);
            acc = fmaf(v.w, s_w0T[(c4*4+3)*32 + o], acc);
        }
        s_lrproj[idx] = acc;
    }
    __syncthreads();

    // ---------------- Phase C: per-pixel MLP, 9 directions ----------------
    float hv[32];
    {
        const float* p = hr + (size_t)b*CC*HH*WW + (size_t)h*WW + w;
#pragma unroll
        for (int c = 0; c < 32; ++c) hv[c] = p[(size_t)c*HH*WW];
    }
    // hrproj = W0_hr @ hr  (shared by all 9 directions)
    float hrp[32];
#pragma unroll
    for (int o = 0; o < 32; ++o) hrp[o] = 0.f;
#pragma unroll
    for (int c = 0; c < 32; ++c) {
        const float v = hv[c];
        const float4* wr = (const float4*)&s_w0T[(32 + c)*32];
#pragma unroll
        for (int o4 = 0; o4 < 8; ++o4) {
            float4 ww = wr[o4];
            hrp[o4*4+0] = fmaf(v, ww.x, hrp[o4*4+0]);
            hrp[o4*4+1] = fmaf(v, ww.y, hrp[o4*4+1]);
            hrp[o4*4+2] = fmaf(v, ww.z, hrp[o4*4+2]);
            hrp[o4*4+3] = fmaf(v, ww.w, hrp[o4*4+3]);
        }
    }

    const int par = ((h & 3) << 2) | (w & 3);
    const int byl = ty >> 2, bxl = tx >> 2;
    // packed (dy+1), (dx+1) per direction
    const unsigned DY1 = (1u<<0)|(1u<<2)|(1u<<4)|(0u<<6)|(2u<<8)|(0u<<10)|(0u<<12)|(2u<<14)|(2u<<16);
    const unsigned DX1 = (1u<<0)|(0u<<2)|(2u<<4)|(1u<<6)|(1u<<8)|(0u<<10)|(2u<<12)|(0u<<14)|(2u<<16);

#pragma unroll 1
    for (int d = 0; d < 9; ++d) {
        const int dy1 = (DY1 >> (2*d)) & 3;
        const int dx1 = (DX1 >> (2*d)) & 3;
        bool valid = true;
        if (dx1 == 0) valid = valid && (w >= 4);
        if (dx1 == 2) valid = valid && (w < WW - 4);
        if (dy1 == 0) valid = valid && (h >= 4);
        if (dy1 == 2) valid = valid && (h < HH - 4);

        const float4* lp = (const float4*)&s_lrproj[((byl + dy1)*10 + (bxl + dx1))*32];
        const float4* bp = (const float4*)&s_bias[(par*9 + d)*32];

        float h0[32];
#pragma unroll
        for (int i4 = 0; i4 < 8; ++i4) {
            float4 l4 = lp[i4];
            float4 b4 = bp[i4];
            float v;
            v = hrp[i4*4+0] + l4.x + b4.x; h0[i4*4+0] = fmaxf(v, 0.01f*v);
            v = hrp[i4*4+1] + l4.y + b4.y; h0[i4*4+1] = fmaxf(v, 0.01f*v);
            v = hrp[i4*4+2] + l4.z + b4.z; h0[i4*4+2] = fmaxf(v, 0.01f*v);
            v = hrp[i4*4+3] + l4.w + b4.w; h0[i4*4+3] = fmaxf(v, 0.01f*v);
        }
        float h1[16];
#pragma unroll
        for (int o = 0; o < 16; ++o) {
            const float4* wr = (const float4*)&s_w1[o*32];
            float a = 0.f;
#pragma unroll
            for (int k4 = 0; k4 < 8; ++k4) {
                float4 ww = wr[k4];
                a = fmaf(ww.x, h0[k4*4+0], a);
                a = fmaf(ww.y, h0[k4*4+1], a);
                a = fmaf(ww.z, h0[k4*4+2], a);
                a = fmaf(ww.w, h0[k4*4+3], a);
            }
            h1[o] = fmaxf(a, 0.01f*a);
        }
        float h2[8];
#pragma unroll
        for (int o = 0; o < 8; ++o) {
            const float4* wr = (const float4*)&s_w2[o*16];
            float a = 0.f;
#pragma unroll
            for (int k4 = 0; k4 < 4; ++k4) {
                float4 ww = wr[k4];
                a = fmaf(ww.x, h1[k4*4+0], a);
                a = fmaf(ww.y, h1[k4*4+1], a);
                a = fmaf(ww.z, h1[k4*4+2], a);
                a = fmaf(ww.w, h1[k4*4+3], a);
            }
            h2[o] = fmaxf(a, 0.01f*a);
        }
        float a = 0.f;
        {
            const float4* wr = (const float4*)s_w3;
            float4 wa = wr[0], wb = wr[1];
            a = fmaf(wa.x, h2[0], a);
            a = fmaf(wa.y, h2[1], a);
            a = fmaf(wa.z, h2[2], a);
            a = fmaf(wa.w, h2[3], a);
            a = fmaf(wb.x, h2[4], a);
            a = fmaf(wb.y, h2[5], a);
            a = fmaf(wb.z, h2[6], a);
            a = fmaf(wb.w, h2[7], a);
        }
        s_logit[d*256 + tid] = valid ? a : -100.0f;
    }

    // ---------------- softmax over the 9 directions ----------------
    float lv[9];
#pragma unroll
    for (int d = 0; d < 9; ++d) lv[d] = s_logit[d*256 + tid];
    float m = lv[0];
#pragma unroll
    for (int d = 1; d < 9; ++d) m = fmaxf(m, lv[d]);
    float ssum = 0.f;
#pragma unroll
    for (int d = 0; d < 9; ++d) { float e = __expf(lv[d] - m); ssum += e; lv[d] = e; }
    const float inv = 1.0f / ssum;
    float* op = out + (size_t)b*9*HH*WW + (size_t)h*WW + w;
#pragma unroll
    for (int d = 0; d < 9; ++d) op[(size_t)d*HH*WW] = lv[d] * inv;
}

extern "C" void kernel_launch(void* const* d_in, const int* in_sizes, int n_in,
                              void* d_out, int out_size) {
    const float* lr = (const float*)d_in[0];
    const float* hr = (const float*)d_in[1];
    // d_in[2], d_in[3] (lr_feature_r / hr_feature_r) are unused by the reference.
    const float* w0 = (const float*)d_in[4];
    const float* w1 = (const float*)d_in[5];
    const float* w2 = (const float*)d_in[6];
    const float* w3 = (const float*)d_in[7];
    dim3 grid(WW/32, HH/8, BB);
    erc_kernel<<<grid, 256>>>(lr, hr, w0, w1, w2, w3, (float*)d_out);
}